// round 2
// baseline (speedup 1.0000x reference)
#include <cuda_runtime.h>
#include <cstdint>

#define NPIX   65536
#define CIMG   256
#define KMASK  9
#define MS     32
#define PITCH  260
#define PROWS  258
#define PPLANE (PROWS*PITCH)   // 67080

// ---------------- scratch (device globals; no allocations allowed) ----------------
__device__ float g_fsm_pad[256*PPLANE];   // padded fsm      (~68.7 MB)
__device__ float g_f1_pad [128*PPLANE];   // padded feat1
__device__ float g_f2_pad [ 64*PPLANE];   // padded feat2
__device__ float g_f3     [ 32*NPIX];     // feat3 (flat)
__device__ float g_wt1    [256*9*128];    // repacked weights [ci][k][co]
__device__ float g_wt2    [128*9*64];
__device__ float g_wt3    [ 64*9*32];
__device__ int   g_bits   [NPIX];         // 9-bit mask membership per pixel
__device__ float g_Spart  [8][KMASK][CIMG];
__device__ int   g_counts [KMASK];
__device__ float g_mean   [KMASK*CIMG];
__device__ unsigned g_validbits;
__device__ float g_covpart[KMASK*16*MS*MS];
__device__ float g_cov    [KMASK*MS*MS];

// ---------------- packed fp32x2 helpers (sm_103a FFMA2) ----------------
__device__ __forceinline__ unsigned long long pk2(float lo, float hi){
    unsigned long long r;
    asm("mov.b64 %0, {%1, %2};" : "=l"(r) : "f"(lo), "f"(hi));
    return r;
}
__device__ __forceinline__ void ffma2(unsigned long long &d, unsigned long long a, unsigned long long b){
    asm("fma.rn.f32x2 %0, %1, %2, %0;" : "+l"(d) : "l"(a), "l"(b));
}

// ---------------- small kernels ----------------
__global__ void k_init(){
    int t = threadIdx.x;
    if (t < KMASK) g_counts[t] = 0;
}

__global__ void k_maskbits(const int* __restrict__ masks){
    int n = blockIdx.x*256 + threadIdx.x;
    int bits = 0;
    #pragma unroll
    for (int k = 0; k < KMASK; k++){
        int on = (masks[k*NPIX + n] > 0) ? 1 : 0;
        bits |= on << k;
        int c = __syncthreads_count(on);
        if (threadIdx.x == 0) atomicAdd(&g_counts[k], c);   // int atomics: deterministic
    }
    g_bits[n] = bits;
}

__global__ void k_sums(const float* __restrict__ x){
    const int c = blockIdx.x, s = blockIdx.y, t = threadIdx.x;
    float ls[KMASK];
    #pragma unroll
    for (int k = 0; k < KMASK; k++) ls[k] = 0.f;
    const float* xc = x + c*NPIX + s*8192;
    const int*   bp = g_bits + s*8192;
    for (int i = 0; i < 32; i++){
        float v = xc[i*256 + t];
        int   b = bp[i*256 + t];
        #pragma unroll
        for (int k = 0; k < KMASK; k++)
            if ((b >> k) & 1) ls[k] += v;
    }
    __shared__ float red[256];
    #pragma unroll
    for (int k = 0; k < KMASK; k++){
        red[t] = ls[k];
        __syncthreads();
        for (int off = 128; off > 0; off >>= 1){
            if (t < off) red[t] += red[t+off];
            __syncthreads();
        }
        if (t == 0) g_Spart[s][k][c] = red[0];
        __syncthreads();
    }
}

__global__ void k_meanvalid(){
    int t = threadIdx.x;   // == channel c, blockDim 256
    for (int k = 0; k < KMASK; k++){
        float s = 0.f;
        #pragma unroll
        for (int p = 0; p < 8; p++) s += g_Spart[p][k][t];
        g_mean[k*CIMG + t] = s / fmaxf((float)g_counts[k], 1.f);
    }
    if (t == 0){
        unsigned vb = 0;
        for (int k = 0; k < KMASK; k++)
            if (g_counts[k] >= 10) vb |= 1u << k;
        g_validbits = vb;
    }
}

__global__ void k_zeroborders(){
    int b = blockIdx.x, t = threadIdx.x;
    float* base;
    if      (b < 256) base = g_fsm_pad + b*PPLANE;
    else if (b < 384) base = g_f1_pad  + (b-256)*PPLANE;
    else              base = g_f2_pad  + (b-384)*PPLANE;
    if (t < 260){ base[t] = 0.f; base[257*PITCH + t] = 0.f; }
    int row = t + 1;   // rows 1..256
    base[row*PITCH + 0]   = 0.f;
    base[row*PITCH + 257] = 0.f;
    base[row*PITCH + 258] = 0.f;
    base[row*PITCH + 259] = 0.f;
}

__global__ void k_repack(const float* __restrict__ w, float* __restrict__ wt, int Cin, int Cout){
    int id = blockIdx.x*256 + threadIdx.x;
    if (id >= Cin*9*Cout) return;
    int co   = id % Cout;
    int rest = id / Cout;           // ci*9 + k
    wt[id] = w[co*(Cin*9) + rest];
}

__global__ void k_fsm(const float* __restrict__ x, float* __restrict__ out_fsm){
    int t = threadIdx.x;
    #pragma unroll 1
    for (int r = 0; r < 8; r++){
        int flat = blockIdx.x*2048 + r*256 + t;   // c*65536 + n
        int c = flat >> 16;
        int n = flat & 65535;
        unsigned ob = ((unsigned)g_bits[n]) & g_validbits;
        float m = 0.f;
        if (ob) m = g_mean[(31 - __clz(ob))*CIMG + c];
        float v = x[flat] - m;
        out_fsm[flat] = v;
        int y = n >> 8, xx = n & 255;
        g_fsm_pad[c*PPLANE + (y+1)*PITCH + (xx+1)] = v;
    }
}

// ---------------- 3x3 conv as implicit GEMM, fp32x2 packed FMA ----------------
// in:  padded [Cin][258][260], wt: [Cin][9][Cout], out: padded or flat.
// block: 256 thr, tile 64(Cout) x 128(px of one image row); BK = 9 (one ci per step).
template<int BM, int MM, bool RELU, bool PADOUT>
__global__ void __launch_bounds__(256) k_conv3x3(
    const float* __restrict__ inp, const float* __restrict__ wt,
    const float* __restrict__ bias, float* __restrict__ outp,
    int Cin, int Cout)
{
    const int t  = threadIdx.x;
    const int tx = t & 15;          // 8 px each
    const int ty = t >> 4;          // MM couts each
    const int y  = blockIdx.x >> 1;
    const int x0 = (blockIdx.x & 1) << 7;
    const int co0 = blockIdx.y * BM;

    __shared__ float As[9][BM];       // As[k][m] = wt[ci][k][co0+m]
    __shared__ float patch[3][132];   // input rows y..y+2, cols x0..x0+131 (padded coords)

    unsigned long long acc[MM/2][8];
    #pragma unroll
    for (int i = 0; i < MM/2; i++)
        #pragma unroll
        for (int j = 0; j < 8; j++) acc[i][j] = 0ull;

    const float* pin = inp + y*PITCH + x0;
    const float* pw  = wt + co0;
    const int NF4A = 9*BM/4;

    #pragma unroll 1
    for (int ci = 0; ci < Cin; ci++){
        __syncthreads();
        if (t < NF4A){
            int k = t / (BM/4), m4 = t % (BM/4);
            *(float4*)&As[k][m4*4] = *(const float4*)&pw[(ci*9 + k)*Cout + m4*4];
        }
        if (t < 99){
            int r = t / 33, c4 = t % 33;
            *(float4*)&patch[r][c4*4] = *(const float4*)&pin[ci*PPLANE + r*PITCH + c4*4];
        }
        __syncthreads();
        #pragma unroll
        for (int dy = 0; dy < 3; dy++){
            float4 p0 = *(const float4*)&patch[dy][tx*8];
            float4 p1 = *(const float4*)&patch[dy][tx*8 + 4];
            float2 p2 = *(const float2*)&patch[dy][tx*8 + 8];
            float rr[10] = {p0.x,p0.y,p0.z,p0.w,p1.x,p1.y,p1.z,p1.w,p2.x,p2.y};
            unsigned long long bb[10];
            #pragma unroll
            for (int v = 0; v < 10; v++) bb[v] = pk2(rr[v], rr[v]);
            #pragma unroll
            for (int dx = 0; dx < 3; dx++){
                const int k = dy*3 + dx;
                unsigned long long a2[MM/2];
                #pragma unroll
                for (int i = 0; i < MM/2; i++)
                    a2[i] = *(const unsigned long long*)&As[k][ty*MM + i*2];
                #pragma unroll
                for (int j = 0; j < 8; j++)
                    #pragma unroll
                    for (int i = 0; i < MM/2; i++)
                        ffma2(acc[i][j], a2[i], bb[dx+j]);
            }
        }
    }

    #pragma unroll
    for (int i = 0; i < MM/2; i++){
        int coA = co0 + ty*MM + 2*i;
        float bA = bias[coA], bB = bias[coA+1];
        #pragma unroll
        for (int j = 0; j < 8; j++){
            float fx, fy;
            asm("mov.b64 {%0, %1}, %2;" : "=f"(fx), "=f"(fy) : "l"(acc[i][j]));
            float vA = fx + bA, vB = fy + bB;
            if (RELU){ vA = fmaxf(vA, 0.f); vB = fmaxf(vB, 0.f); }
            int xg = x0 + tx*8 + j;
            if (PADOUT){
                outp[ coA   *PPLANE + (y+1)*PITCH + (xg+1)] = vA;
                outp[(coA+1)*PPLANE + (y+1)*PITCH + (xg+1)] = vB;
            } else {
                outp[ coA   *NPIX + y*256 + xg] = vA;
                outp[(coA+1)*NPIX + y*256 + xg] = vB;
            }
        }
    }
}

// ---------------- masked 32x32 covariance (deterministic partials) ----------------
__global__ void __launch_bounds__(256) k_cov(const float* __restrict__ f3){
    const int k = blockIdx.y;
    const int chunk = blockIdx.x;        // 16 chunks of 4096 px
    const int n0 = chunk*4096;
    const int t = threadIdx.x;
    __shared__ float ftile[32*257];      // [c][p], stride 257 (odd -> conflict-free)
    const int pt = t & 63, pg = t >> 6;
    const int ci0 = (pt & 7)*4, di0 = (pt >> 3)*4;

    float acc[4][4];
    #pragma unroll
    for (int a = 0; a < 4; a++)
        #pragma unroll
        for (int b = 0; b < 4; b++) acc[a][b] = 0.f;

    #pragma unroll 1
    for (int st = 0; st < 16; st++){
        int nb = n0 + st*256;
        __syncthreads();
        float mk = ((g_bits[nb + t] >> k) & 1) ? 1.f : 0.f;
        #pragma unroll
        for (int c = 0; c < 32; c++)
            ftile[c*257 + t] = f3[c*NPIX + nb + t] * mk;
        __syncthreads();
        for (int p = pg; p < 256; p += 4){
            float fc[4], fd[4];
            #pragma unroll
            for (int q = 0; q < 4; q++){
                fc[q] = ftile[(ci0+q)*257 + p];
                fd[q] = ftile[(di0+q)*257 + p];
            }
            #pragma unroll
            for (int a = 0; a < 4; a++)
                #pragma unroll
                for (int b = 0; b < 4; b++)
                    acc[a][b] += fd[a]*fc[b];
        }
    }
    __syncthreads();
    float* red = ftile;                  // reuse smem
    #pragma unroll
    for (int a = 0; a < 4; a++)
        #pragma unroll
        for (int b = 0; b < 4; b++)
            red[(pg*64 + pt)*16 + a*4 + b] = acc[a][b];
    __syncthreads();
    if (pg == 0){
        #pragma unroll
        for (int e = 0; e < 16; e++){
            float s = red[pt*16+e] + red[(64+pt)*16+e] + red[(128+pt)*16+e] + red[(192+pt)*16+e];
            int a = e >> 2, b = e & 3;
            g_covpart[(k*16 + chunk)*1024 + (di0+a)*32 + (ci0+b)] = s;
        }
    }
}

__global__ void k_covreduce(){
    int e = blockIdx.x*256 + threadIdx.x;    // 9216
    int k = e >> 10;
    float s = 0.f;
    #pragma unroll
    for (int ch = 0; ch < 16; ch++) s += g_covpart[(k*16 + ch)*1024 + (e & 1023)];
    g_cov[e] = s / fmaxf((float)g_counts[k], 1.f);
}

__global__ void k_trans(const float* __restrict__ fcw, const float* __restrict__ fcb,
                        float* __restrict__ out){
    int gid = blockIdx.x*256 + threadIdx.x;  // 9216
    int k = gid >> 10, j = gid & 1023;
    float s = fcb[j];
    const float* cv = g_cov + k*1024;
    const float* wr = fcw + j*1024;
    #pragma unroll 8
    for (int i = 0; i < 1024; i++) s += cv[i]*wr[i];
    if (g_counts[k] < 10) s = 0.f;
    out[gid] = s;
}

// ---------------- launcher ----------------
extern "C" void kernel_launch(void* const* d_in, const int* in_sizes, int n_in,
                              void* d_out, int out_size)
{
    const float* x     = (const float*)d_in[0];
    const int*   masks = (const int*)  d_in[1];
    const float* w1    = (const float*)d_in[2];
    const float* b1    = (const float*)d_in[3];
    const float* w2    = (const float*)d_in[4];
    const float* b2    = (const float*)d_in[5];
    const float* w3    = (const float*)d_in[6];
    const float* b3    = (const float*)d_in[7];
    const float* fcw   = (const float*)d_in[8];
    const float* fcb   = (const float*)d_in[9];

    float* out       = (float*)d_out;
    float* out_trans = out;                       // [9][1024]
    float* out_fsm   = out + KMASK*MS*MS;         // [256][65536]

    void *p;
    cudaGetSymbolAddress(&p, g_fsm_pad); float* fsm_pad = (float*)p;
    cudaGetSymbolAddress(&p, g_f1_pad);  float* f1      = (float*)p;
    cudaGetSymbolAddress(&p, g_f2_pad);  float* f2      = (float*)p;
    cudaGetSymbolAddress(&p, g_f3);      float* f3      = (float*)p;
    cudaGetSymbolAddress(&p, g_wt1);     float* wt1     = (float*)p;
    cudaGetSymbolAddress(&p, g_wt2);     float* wt2     = (float*)p;
    cudaGetSymbolAddress(&p, g_wt3);     float* wt3     = (float*)p;

    k_init<<<1, 32>>>();
    k_maskbits<<<256, 256>>>(masks);
    k_sums<<<dim3(256, 8), 256>>>(x);
    k_meanvalid<<<1, 256>>>();
    k_zeroborders<<<448, 256>>>();
    k_repack<<<(256*9*128 + 255)/256, 256>>>(w1, wt1, 256, 128);
    k_repack<<<(128*9*64  + 255)/256, 256>>>(w2, wt2, 128, 64);
    k_repack<<<( 64*9*32  + 255)/256, 256>>>(w3, wt3, 64, 32);
    k_fsm<<<8192, 256>>>(x, out_fsm);

    k_conv3x3<64, 4, true,  true ><<<dim3(512, 2), 256>>>(fsm_pad, wt1, b1, f1, 256, 128);
    k_conv3x3<64, 4, true,  true ><<<dim3(512, 1), 256>>>(f1,      wt2, b2, f2, 128,  64);
    k_conv3x3<32, 2, false, false><<<dim3(512, 1), 256>>>(f2,      wt3, b3, f3,  64,  32);

    k_cov<<<dim3(16, 9), 256>>>(f3);
    k_covreduce<<<36, 256>>>();
    k_trans<<<36, 256>>>(fcw, fcb, out_trans);
}

// round 5
// speedup vs baseline: 1.4734x; 1.4734x over previous
#include <cuda_runtime.h>
#include <cuda_bf16.h>
#include <cstdint>

#define NPIX  65536
#define KMASK 9

// ---------------- device-global scratch ----------------
__device__ __nv_bfloat16 g_xbh[(size_t)NPIX*256];   // fsm bf16 HWC hi
__device__ __nv_bfloat16 g_xbl[(size_t)NPIX*256];   // fsm bf16 HWC lo
__device__ __nv_bfloat16 g_f1h[(size_t)NPIX*128];
__device__ __nv_bfloat16 g_f1l[(size_t)NPIX*128];
__device__ __nv_bfloat16 g_f2h[(size_t)NPIX*64];
__device__ __nv_bfloat16 g_f2l[(size_t)NPIX*64];
__device__ float         g_f3 [32*NPIX];            // feat3 fp32 [c][n]
__device__ __nv_bfloat16 g_wA1[16*9*128*32];        // [s*2+sel][tap][co][ci32]
__device__ __nv_bfloat16 g_wA2[8*9*64*32];
__device__ __nv_bfloat16 g_wA3[4*9*32*32];
__device__ int   g_bits  [NPIX];
__device__ float g_Spart [8][KMASK][256];
__device__ int   g_counts[KMASK];
__device__ float g_mean  [KMASK*256];
__device__ unsigned g_validbits;
__device__ float g_covpart[KMASK*16*1024];
__device__ float g_cov    [KMASK*1024];

// ---------------- helpers ----------------
__device__ __forceinline__ uint32_t s2u(const void* p){
    uint32_t a;
    asm("{ .reg .u64 t; cvta.to.shared.u64 t, %1; cvt.u32.u64 %0, t; }" : "=r"(a) : "l"(p));
    return a;
}
__device__ __forceinline__ uint32_t swz(uint32_t b){   // kill 64B-stride ldmatrix conflicts
    return b ^ (((b >> 7) & 3u) << 4);
}
__device__ __forceinline__ void ldsm4(uint32_t* r, uint32_t addr){
    asm volatile("ldmatrix.sync.aligned.m8n8.x4.shared.b16 {%0,%1,%2,%3}, [%4];"
        : "=r"(r[0]), "=r"(r[1]), "=r"(r[2]), "=r"(r[3]) : "r"(addr));
}
__device__ __forceinline__ void mma16816(float* c, const uint32_t* a, uint32_t b0, uint32_t b1){
    asm volatile("mma.sync.aligned.m16n8k16.row.col.f32.bf16.bf16.f32 "
        "{%0,%1,%2,%3},{%4,%5,%6,%7},{%8,%9},{%0,%1,%2,%3};"
        : "+f"(c[0]), "+f"(c[1]), "+f"(c[2]), "+f"(c[3])
        : "r"(a[0]), "r"(a[1]), "r"(a[2]), "r"(a[3]), "r"(b0), "r"(b1));
}

// ---------------- small kernels ----------------
__global__ void k_init(){
    if (threadIdx.x < KMASK) g_counts[threadIdx.x] = 0;
}
__global__ void k_maskbits(const int* __restrict__ masks){
    int n = blockIdx.x*256 + threadIdx.x;
    int bits = 0;
    #pragma unroll
    for (int k = 0; k < KMASK; k++){
        int on = (masks[k*NPIX + n] > 0) ? 1 : 0;
        bits |= on << k;
        int c = __syncthreads_count(on);
        if (threadIdx.x == 0) atomicAdd(&g_counts[k], c);
    }
    g_bits[n] = bits;
}
__global__ void k_sums(const float* __restrict__ x){
    const int c = blockIdx.x, s = blockIdx.y, t = threadIdx.x;
    float ls[KMASK];
    #pragma unroll
    for (int k = 0; k < KMASK; k++) ls[k] = 0.f;
    const float* xc = x + c*NPIX + s*8192;
    const int*   bp = g_bits + s*8192;
    for (int i = 0; i < 32; i++){
        float v = xc[i*256 + t];
        int   b = bp[i*256 + t];
        #pragma unroll
        for (int k = 0; k < KMASK; k++)
            if ((b >> k) & 1) ls[k] += v;
    }
    __shared__ float red[256];
    #pragma unroll
    for (int k = 0; k < KMASK; k++){
        red[t] = ls[k];
        __syncthreads();
        for (int off = 128; off > 0; off >>= 1){
            if (t < off) red[t] += red[t+off];
            __syncthreads();
        }
        if (t == 0) g_Spart[s][k][c] = red[0];
        __syncthreads();
    }
}
__global__ void k_meanvalid(){
    int t = threadIdx.x;
    for (int k = 0; k < KMASK; k++){
        float s = 0.f;
        #pragma unroll
        for (int p = 0; p < 8; p++) s += g_Spart[p][k][t];
        g_mean[k*256 + t] = s / fmaxf((float)g_counts[k], 1.f);
    }
    if (t == 0){
        unsigned vb = 0;
        for (int k = 0; k < KMASK; k++)
            if (g_counts[k] >= 10) vb |= 1u << k;
        g_validbits = vb;
    }
}

// fsm: fp32 [c][n] out + bf16 hi/lo HWC planes
__global__ void k_fsm(const float* __restrict__ x, float* __restrict__ out_fsm){
    int n = blockIdx.x*256 + threadIdx.x;
    unsigned ob = ((unsigned)g_bits[n]) & g_validbits;
    int krow = ob ? (31 - __clz(ob)) : -1;
    #pragma unroll 1
    for (int g = 0; g < 32; g++){
        __nv_bfloat16 bh[8], bl[8];
        #pragma unroll
        for (int j = 0; j < 8; j++){
            int c = g*8 + j;
            float m = (krow >= 0) ? g_mean[krow*256 + c] : 0.f;
            float v = x[c*NPIX + n] - m;
            out_fsm[c*NPIX + n] = v;
            __nv_bfloat16 h = __float2bfloat16(v);
            bh[j] = h;
            bl[j] = __float2bfloat16(v - __bfloat162float(h));
        }
        *(uint4*)&g_xbh[(size_t)n*256 + g*8] = *(uint4*)bh;
        *(uint4*)&g_xbl[(size_t)n*256 + g*8] = *(uint4*)bl;
    }
}

// weights -> [s*2+sel][tap][co][ci32] bf16 (sel 0 = hi, 1 = lo residual)
__global__ void k_repackW(const float* __restrict__ w, __nv_bfloat16* __restrict__ wA,
                          int Cin, int Cout, int total){
    int idx = blockIdx.x*256 + threadIdx.x;
    if (idx >= total) return;
    int kci = idx & 31;
    int co  = (idx >> 5) % Cout;
    int r   = idx / (32*Cout);         // (s*2+sel)*9 + tap
    int tap = r % 9;
    int ss  = r / 9;                   // s*2 + sel
    int sel = ss & 1, s = ss >> 1;
    float v = w[(co*Cin + s*32 + kci)*9 + tap];
    __nv_bfloat16 h = __float2bfloat16(v);
    wA[idx] = sel ? __float2bfloat16(v - __bfloat162float(h)) : h;
}

// ---------------- HMMA implicit-GEMM 3x3 conv, 3-term bf16 compensation ----------------
// chunk sp: s = sp/3, tt = sp%3. tt0: B=hi,A=wh; tt1: B=hi(keep),A=wl; tt2: B=lo,A=wh.
template<int CIN, int COUT, int WN, int MW, bool RELU, int OMODE>
__global__ void __launch_bounds__(256, 2) k_convmma(
    const __nv_bfloat16* __restrict__ inh, const __nv_bfloat16* __restrict__ inl,
    const __nv_bfloat16* __restrict__ wA, const float* __restrict__ bias,
    float* __restrict__ outf, __nv_bfloat16* __restrict__ outbh, __nv_bfloat16* __restrict__ outbl)
{
    constexpr int S   = CIN/32;
    constexpr int XT  = WN*32;
    constexpr int PXW = XT + 4;
    constexpr int ASZ = 9*COUT*64;     // bytes
    constexpr int MT  = MW/16;
    constexpr int NB4 = 3*PXW*4;
    constexpr int NA4 = 9*COUT*4;

    extern __shared__ __align__(1024) char sm[];
    const uint32_t smb = s2u(sm);
    const int t = threadIdx.x, w = t >> 5, lane = t & 31;
    const int wm = w / WN, wn = w % WN;
    const int mbase = wm*MW, nbase = wn*32;
    const int y = blockIdx.y, x0 = blockIdx.x*XT;
    const int g = lane >> 2, tr = lane & 3;
    const int a_row = lane & 15, a_kh = lane >> 4;
    const int b_n = (lane & 7) + ((lane >> 4) << 3), b_kh = (lane >> 3) & 1;

    float acc[MT][4][4];
    #pragma unroll
    for (int mi = 0; mi < MT; mi++)
        #pragma unroll
        for (int ni = 0; ni < 4; ni++)
            #pragma unroll
            for (int q = 0; q < 4; q++) acc[mi][ni][q] = 0.f;

    #pragma unroll 1
    for (int sp = 0; sp < 3*S; sp++){
        const int s  = sp/3;
        const int tt = sp - 3*s;
        __syncthreads();
        if (tt != 1){
            const __nv_bfloat16* bsrc = (tt == 2) ? inl : inh;
            const int cb = s*32;
            #pragma unroll 1
            for (int idx = t; idx < NB4; idx += 256){
                int kcq = idx & 3, p = idx >> 2;
                int d = p / PXW, h = p - d*PXW;
                int r = y + d - 1, gx = x0 + h - 1;
                uint4 v = make_uint4(0u,0u,0u,0u);
                if (h < XT+2 && (unsigned)r < 256u && (unsigned)gx < 256u)
                    v = *(const uint4*)(bsrc + ((size_t)(r*256 + gx))*CIN + cb + kcq*8);
                *(uint4*)(sm + ASZ + swz((uint32_t)(p*64 + kcq*16))) = v;
            }
        }
        const uint4* ws = (const uint4*)wA + (size_t)(s*2 + (tt == 1))*NA4;
        #pragma unroll 1
        for (int idx = t; idx < NA4; idx += 256)
            *(uint4*)(sm + swz((uint32_t)idx*16)) = ws[idx];
        __syncthreads();

        #pragma unroll
        for (int kk = 0; kk < 32; kk += 16){
            #pragma unroll
            for (int tap = 0; tap < 9; tap++){
                const int dy = tap/3, dx = tap - dy*3;
                uint32_t af[MT][4], bf[2][4];
                #pragma unroll
                for (int mi = 0; mi < MT; mi++){
                    uint32_t la = (uint32_t)(((tap*COUT + mbase + mi*16 + a_row)*32 + kk + a_kh*8)*2);
                    ldsm4(af[mi], smb + swz(la));
                }
                #pragma unroll
                for (int nh = 0; nh < 2; nh++){
                    uint32_t lb = (uint32_t)(((dy*PXW + nbase + nh*16 + b_n + dx)*32 + kk + b_kh*8)*2);
                    ldsm4(bf[nh], smb + ASZ + swz(lb));
                }
                #pragma unroll
                for (int mi = 0; mi < MT; mi++)
                    #pragma unroll
                    for (int ni = 0; ni < 4; ni++)
                        mma16816(acc[mi][ni], af[mi], bf[ni>>1][(ni&1)*2], bf[ni>>1][(ni&1)*2 + 1]);
            }
        }
    }

    __syncthreads();
    if (OMODE == 0){
        __nv_bfloat16* tile = (__nv_bfloat16*)sm;     // [XT][COUT]
        // pass 0: hi plane; pass 1: lo plane
        #pragma unroll 1
        for (int pass = 0; pass < 2; pass++){
            #pragma unroll
            for (int mi = 0; mi < MT; mi++){
                int m0 = mbase + mi*16 + g;
                float b0v = bias[m0], b1v = bias[m0+8];
                #pragma unroll
                for (int ni = 0; ni < 4; ni++){
                    int n = nbase + ni*8 + 2*tr;
                    float v00 = acc[mi][ni][0] + b0v, v01 = acc[mi][ni][1] + b0v;
                    float v10 = acc[mi][ni][2] + b1v, v11 = acc[mi][ni][3] + b1v;
                    if (RELU){ v00=fmaxf(v00,0.f); v01=fmaxf(v01,0.f); v10=fmaxf(v10,0.f); v11=fmaxf(v11,0.f); }
                    __nv_bfloat16 h00 = __float2bfloat16(v00), h01 = __float2bfloat16(v01);
                    __nv_bfloat16 h10 = __float2bfloat16(v10), h11 = __float2bfloat16(v11);
                    if (pass == 1){
                        h00 = __float2bfloat16(v00 - __bfloat162float(h00));
                        h01 = __float2bfloat16(v01 - __bfloat162float(h01));
                        h10 = __float2bfloat16(v10 - __bfloat162float(h10));
                        h11 = __float2bfloat16(v11 - __bfloat162float(h11));
                    }
                    tile[ n   *COUT + m0    ] = h00;
                    tile[(n+1)*COUT + m0    ] = h01;
                    tile[ n   *COUT + m0 + 8] = h10;
                    tile[(n+1)*COUT + m0 + 8] = h11;
                }
            }
            __syncthreads();
            uint4* dst = (uint4*)((pass ? outbl : outbh) + (size_t)(y*256 + x0)*COUT);
            const uint4* src = (const uint4*)sm;
            #pragma unroll 1
            for (int i = t; i < XT*COUT/8; i += 256) dst[i] = src[i];
            __syncthreads();
        }
    } else {
        float* tile = (float*)sm;                     // [XT][33]
        #pragma unroll
        for (int mi = 0; mi < MT; mi++){
            int m0 = mbase + mi*16 + g;
            float b0v = bias[m0], b1v = bias[m0+8];
            #pragma unroll
            for (int ni = 0; ni < 4; ni++){
                int n = nbase + ni*8 + 2*tr;
                float v00 = acc[mi][ni][0] + b0v, v01 = acc[mi][ni][1] + b0v;
                float v10 = acc[mi][ni][2] + b1v, v11 = acc[mi][ni][3] + b1v;
                if (RELU){ v00=fmaxf(v00,0.f); v01=fmaxf(v01,0.f); v10=fmaxf(v10,0.f); v11=fmaxf(v11,0.f); }
                tile[ n   *33 + m0    ] = v00;
                tile[(n+1)*33 + m0    ] = v01;
                tile[ n   *33 + m0 + 8] = v10;
                tile[(n+1)*33 + m0 + 8] = v11;
            }
        }
        __syncthreads();
        #pragma unroll 1
        for (int co = 0; co < COUT; co++)
            outf[(size_t)co*NPIX + y*256 + t] = tile[t*33 + co];
    }
}

// ---------------- masked covariance + FC ----------------
__global__ void __launch_bounds__(256) k_cov(const float* __restrict__ f3){
    const int k = blockIdx.y;
    const int chunk = blockIdx.x;
    const int n0 = chunk*4096;
    const int t = threadIdx.x;
    __shared__ float ftile[32*257];
    const int pt = t & 63, pg = t >> 6;
    const int ci0 = (pt & 7)*4, di0 = (pt >> 3)*4;
    float acc[4][4];
    #pragma unroll
    for (int a = 0; a < 4; a++)
        #pragma unroll
        for (int b = 0; b < 4; b++) acc[a][b] = 0.f;
    #pragma unroll 1
    for (int st = 0; st < 16; st++){
        int nb = n0 + st*256;
        __syncthreads();
        float mk = ((g_bits[nb + t] >> k) & 1) ? 1.f : 0.f;
        #pragma unroll
        for (int c = 0; c < 32; c++)
            ftile[c*257 + t] = f3[c*NPIX + nb + t] * mk;
        __syncthreads();
        for (int p = pg; p < 256; p += 4){
            float fc[4], fd[4];
            #pragma unroll
            for (int q = 0; q < 4; q++){
                fc[q] = ftile[(ci0+q)*257 + p];
                fd[q] = ftile[(di0+q)*257 + p];
            }
            #pragma unroll
            for (int a = 0; a < 4; a++)
                #pragma unroll
                for (int b = 0; b < 4; b++)
                    acc[a][b] += fd[a]*fc[b];
        }
    }
    __syncthreads();
    float* red = ftile;
    #pragma unroll
    for (int a = 0; a < 4; a++)
        #pragma unroll
        for (int b = 0; b < 4; b++)
            red[(pg*64 + pt)*16 + a*4 + b] = acc[a][b];
    __syncthreads();
    if (pg == 0){
        #pragma unroll
        for (int e = 0; e < 16; e++){
            float s = red[pt*16+e] + red[(64+pt)*16+e] + red[(128+pt)*16+e] + red[(192+pt)*16+e];
            int a = e >> 2, b = e & 3;
            g_covpart[(k*16 + chunk)*1024 + (di0+a)*32 + (ci0+b)] = s;
        }
    }
}
__global__ void k_covreduce(){
    int e = blockIdx.x*256 + threadIdx.x;
    int k = e >> 10;
    float s = 0.f;
    #pragma unroll
    for (int ch = 0; ch < 16; ch++) s += g_covpart[(k*16 + ch)*1024 + (e & 1023)];
    g_cov[e] = s / fmaxf((float)g_counts[k], 1.f);
}
__global__ void k_trans(const float* __restrict__ fcw, const float* __restrict__ fcb,
                        float* __restrict__ out){
    int gid = blockIdx.x*256 + threadIdx.x;
    int k = gid >> 10, j = gid & 1023;
    float s = fcb[j];
    const float* cv = g_cov + k*1024;
    const float* wr = fcw + j*1024;
    #pragma unroll 8
    for (int i = 0; i < 1024; i++) s += cv[i]*wr[i];
    if (g_counts[k] < 10) s = 0.f;
    out[gid] = s;
}

// ---------------- launcher ----------------
extern "C" void kernel_launch(void* const* d_in, const int* in_sizes, int n_in,
                              void* d_out, int out_size)
{
    const float* x     = (const float*)d_in[0];
    const int*   masks = (const int*)  d_in[1];
    const float* w1    = (const float*)d_in[2];
    const float* b1    = (const float*)d_in[3];
    const float* w2    = (const float*)d_in[4];
    const float* b2    = (const float*)d_in[5];
    const float* w3    = (const float*)d_in[6];
    const float* b3    = (const float*)d_in[7];
    const float* fcw   = (const float*)d_in[8];
    const float* fcb   = (const float*)d_in[9];

    float* out       = (float*)d_out;
    float* out_trans = out;
    float* out_fsm   = out + KMASK*32*32;

    void* p;
    cudaGetSymbolAddress(&p, g_xbh); __nv_bfloat16* xbh = (__nv_bfloat16*)p;
    cudaGetSymbolAddress(&p, g_xbl); __nv_bfloat16* xbl = (__nv_bfloat16*)p;
    cudaGetSymbolAddress(&p, g_f1h); __nv_bfloat16* f1h = (__nv_bfloat16*)p;
    cudaGetSymbolAddress(&p, g_f1l); __nv_bfloat16* f1l = (__nv_bfloat16*)p;
    cudaGetSymbolAddress(&p, g_f2h); __nv_bfloat16* f2h = (__nv_bfloat16*)p;
    cudaGetSymbolAddress(&p, g_f2l); __nv_bfloat16* f2l = (__nv_bfloat16*)p;
    cudaGetSymbolAddress(&p, g_f3);  float*         f3  = (float*)p;
    cudaGetSymbolAddress(&p, g_wA1); __nv_bfloat16* wA1 = (__nv_bfloat16*)p;
    cudaGetSymbolAddress(&p, g_wA2); __nv_bfloat16* wA2 = (__nv_bfloat16*)p;
    cudaGetSymbolAddress(&p, g_wA3); __nv_bfloat16* wA3 = (__nv_bfloat16*)p;

    const int SM1 = 9*128*64 + 3*132*64;   // 99072
    const int SM2 = 9*64*64  + 3*260*64;   // 86784
    const int SM3 = 9*32*64  + 3*260*64;   // 68352

    cudaFuncSetAttribute(k_convmma<256,128,4,64,true ,0>, cudaFuncAttributeMaxDynamicSharedMemorySize, SM1);
    cudaFuncSetAttribute(k_convmma<128, 64,8,64,true ,0>, cudaFuncAttributeMaxDynamicSharedMemorySize, SM2);
    cudaFuncSetAttribute(k_convmma< 64, 32,8,32,false,1>, cudaFuncAttributeMaxDynamicSharedMemorySize, SM3);

    k_init<<<1, 32>>>();
    k_maskbits<<<256, 256>>>(masks);
    k_sums<<<dim3(256, 8), 256>>>(x);
    k_meanvalid<<<1, 256>>>();
    k_repackW<<<(16*9*128*32)/256, 256>>>(w1, wA1, 256, 128, 16*9*128*32);
    k_repackW<<<( 8*9*64*32 )/256, 256>>>(w2, wA2, 128,  64,  8*9*64*32);
    k_repackW<<<( 4*9*32*32 )/256, 256>>>(w3, wA3,  64,  32,  4*9*32*32);
    k_fsm<<<256, 256>>>(x, out_fsm);

    k_convmma<256,128,4,64,true ,0><<<dim3(2,256), 256, SM1>>>(xbh, xbl, wA1, b1, nullptr, f1h, f1l);
    k_convmma<128, 64,8,64,true ,0><<<dim3(1,256), 256, SM2>>>(f1h, f1l, wA2, b2, nullptr, f2h, f2l);
    k_convmma< 64, 32,8,32,false,1><<<dim3(1,256), 256, SM3>>>(f2h, f2l, wA3, b3, f3, nullptr, nullptr);

    k_cov<<<dim3(16, 9), 256>>>(f3);
    k_covreduce<<<36, 256>>>();
    k_trans<<<36, 256>>>(fcw, fcb, out_trans);
}

// round 6
// speedup vs baseline: 2.7435x; 1.8621x over previous
#include <cuda_runtime.h>
#include <cuda_fp16.h>
#include <cstdint>

#define NPIX  65536
#define KMASK 9

// ---------------- device-global scratch ----------------
__device__ __align__(16) __half g_xb [(size_t)NPIX*256];   // fsm fp16 HWC
__device__ __align__(16) __half g_f1 [(size_t)NPIX*128];   // feat1 fp16 HWC
__device__ __align__(16) __half g_f2 [(size_t)NPIX*64];    // feat2 fp16 HWC
__device__ float  g_f3 [32*NPIX];                          // feat3 fp32 [c][n]
__device__ __align__(16) __half g_wA1[16*9*128*32];        // [s*2+sel][tap][co][ci32]
__device__ __align__(16) __half g_wA2[8*9*64*32];
__device__ __align__(16) __half g_wA3[4*9*32*32];
__device__ int   g_bits  [NPIX];
__device__ int   g_cntpart[256][KMASK];
__device__ float g_Spart [8][KMASK][256];
__device__ int   g_counts[KMASK];
__device__ float g_mean  [KMASK*256];
__device__ unsigned g_validbits;
__device__ float g_covpart[KMASK*16*1024];
__device__ float g_cov    [KMASK*1024];

// ---------------- helpers ----------------
__device__ __forceinline__ uint32_t s2u(const void* p){
    uint32_t a;
    asm("{ .reg .u64 t; cvta.to.shared.u64 t, %1; cvt.u32.u64 %0, t; }" : "=r"(a) : "l"(p));
    return a;
}
__device__ __forceinline__ uint32_t swz(uint32_t b){   // kill 64B-stride ldmatrix conflicts
    return b ^ (((b >> 7) & 3u) << 4);
}
__device__ __forceinline__ void ldsm4(uint32_t* r, uint32_t addr){
    asm volatile("ldmatrix.sync.aligned.m8n8.x4.shared.b16 {%0,%1,%2,%3}, [%4];"
        : "=r"(r[0]), "=r"(r[1]), "=r"(r[2]), "=r"(r[3]) : "r"(addr));
}
__device__ __forceinline__ void mma16816(float* c, const uint32_t* a, uint32_t b0, uint32_t b1){
    asm volatile("mma.sync.aligned.m16n8k16.row.col.f32.f16.f16.f32 "
        "{%0,%1,%2,%3},{%4,%5,%6,%7},{%8,%9},{%0,%1,%2,%3};"
        : "+f"(c[0]), "+f"(c[1]), "+f"(c[2]), "+f"(c[3])
        : "r"(a[0]), "r"(a[1]), "r"(a[2]), "r"(a[3]), "r"(b0), "r"(b1));
}
__device__ __forceinline__ void cpa16(uint32_t s, const void* g){
    asm volatile("cp.async.cg.shared.global [%0], [%1], 16;" :: "r"(s), "l"(g));
}
__device__ __forceinline__ void cpa_wait(){
    asm volatile("cp.async.commit_group;");
    asm volatile("cp.async.wait_group 0;");
}

// ---------------- small kernels ----------------
__global__ void k_maskbits(const int* __restrict__ masks){
    int n = blockIdx.x*256 + threadIdx.x;
    int bits = 0;
    #pragma unroll
    for (int k = 0; k < KMASK; k++){
        int on = (masks[k*NPIX + n] > 0) ? 1 : 0;
        bits |= on << k;
        int c = __syncthreads_count(on);
        if (threadIdx.x == 0) g_cntpart[blockIdx.x][k] = c;   // deterministic partials
    }
    g_bits[n] = bits;
}
__global__ void k_sums(const float* __restrict__ x){
    const int c = blockIdx.x, s = blockIdx.y, t = threadIdx.x;
    float ls[KMASK];
    #pragma unroll
    for (int k = 0; k < KMASK; k++) ls[k] = 0.f;
    const float* xc = x + c*NPIX + s*8192;
    const int*   bp = g_bits + s*8192;
    for (int i = 0; i < 32; i++){
        float v = xc[i*256 + t];
        int   b = bp[i*256 + t];
        #pragma unroll
        for (int k = 0; k < KMASK; k++)
            if ((b >> k) & 1) ls[k] += v;
    }
    __shared__ float red[256];
    #pragma unroll
    for (int k = 0; k < KMASK; k++){
        red[t] = ls[k];
        __syncthreads();
        for (int off = 128; off > 0; off >>= 1){
            if (t < off) red[t] += red[t+off];
            __syncthreads();
        }
        if (t == 0) g_Spart[s][k][c] = red[0];
        __syncthreads();
    }
}
__global__ void k_meanvalid(){
    int t = threadIdx.x;
    __shared__ int redi[256];
    __shared__ int scnt[KMASK];
    for (int k = 0; k < KMASK; k++){
        redi[t] = g_cntpart[t][k];
        __syncthreads();
        for (int off = 128; off > 0; off >>= 1){
            if (t < off) redi[t] += redi[t+off];
            __syncthreads();
        }
        if (t == 0){ scnt[k] = redi[0]; g_counts[k] = redi[0]; }
        __syncthreads();
    }
    for (int k = 0; k < KMASK; k++){
        float s = 0.f;
        #pragma unroll
        for (int p = 0; p < 8; p++) s += g_Spart[p][k][t];
        g_mean[k*256 + t] = s / fmaxf((float)scnt[k], 1.f);
    }
    if (t == 0){
        unsigned vb = 0;
        for (int k = 0; k < KMASK; k++)
            if (scnt[k] >= 10) vb |= 1u << k;
        g_validbits = vb;
    }
}

// fsm: fp32 [c][n] out + fp16 HWC plane
__global__ void k_fsm(const float* __restrict__ x, float* __restrict__ out_fsm){
    int n = blockIdx.x*256 + threadIdx.x;
    unsigned ob = ((unsigned)g_bits[n]) & g_validbits;
    int krow = ob ? (31 - __clz(ob)) : -1;
    #pragma unroll 1
    for (int g = 0; g < 32; g++){
        __half bh[8];
        #pragma unroll
        for (int j = 0; j < 8; j++){
            int c = g*8 + j;
            float m = (krow >= 0) ? g_mean[krow*256 + c] : 0.f;
            float v = x[c*NPIX + n] - m;
            out_fsm[c*NPIX + n] = v;
            bh[j] = __float2half(v);
        }
        *(uint4*)&g_xb[(size_t)n*256 + g*8] = *(uint4*)bh;
    }
}

// all weights -> [s*2+sel][tap][co][ci32] fp16 (sel 0 = hi, 1 = lo residual)
__global__ void k_repackAll(const float* __restrict__ w1, const float* __restrict__ w2,
                            const float* __restrict__ w3){
    const int N1 = 16*9*128*32, N2 = 8*9*64*32, N3 = 4*9*32*32;
    int id = blockIdx.x*256 + threadIdx.x;
    const float* w; __half* wA; int Cin, Cout, idx;
    if (id < N1)            { w = w1; wA = g_wA1; Cin = 256; Cout = 128; idx = id; }
    else if (id < N1+N2)    { w = w2; wA = g_wA2; Cin = 128; Cout =  64; idx = id - N1; }
    else if (id < N1+N2+N3) { w = w3; wA = g_wA3; Cin =  64; Cout =  32; idx = id - N1 - N2; }
    else return;
    int kci = idx & 31;
    int co  = (idx >> 5) % Cout;
    int r   = idx / (32*Cout);         // (s*2+sel)*9 + tap
    int tap = r % 9;
    int ss  = r / 9;
    int sel = ss & 1, s = ss >> 1;
    float v = w[(co*Cin + s*32 + kci)*9 + tap];
    __half h = __float2half(v);
    wA[idx] = sel ? __float2half(v - __half2float(h)) : h;
}

// ---------------- HMMA implicit-GEMM 3x3 conv, fp16 2-term (w = wh + wl) ----------------
// chunk sp: s = sp>>1, tt = sp&1. tt0: fill B, A=wh; tt1: keep B, A=wl.
template<int CIN, int COUT, int WN, int MW, bool RELU, int OMODE>
__global__ void __launch_bounds__(256, 2) k_convmma(
    const __half* __restrict__ in, const __half* __restrict__ wA,
    const float* __restrict__ bias, float* __restrict__ outf, __half* __restrict__ outb)
{
    constexpr int S   = CIN/32;
    constexpr int XT  = WN*32;
    constexpr int PXW = XT + 4;
    constexpr int ASZ = 9*COUT*64;     // bytes
    constexpr int MT  = MW/16;
    constexpr int NB4 = 3*PXW*4;
    constexpr int NA4 = 9*COUT*4;

    extern __shared__ __align__(1024) char sm[];
    const uint32_t smb = s2u(sm);
    const int t = threadIdx.x, w = t >> 5, lane = t & 31;
    const int wm = w / WN, wn = w % WN;
    const int mbase = wm*MW, nbase = wn*32;
    const int y = blockIdx.y, x0 = blockIdx.x*XT;
    const int g = lane >> 2, tr = lane & 3;
    const int a_row = lane & 15, a_kh = lane >> 4;
    const int b_n = (lane & 7) + ((lane >> 4) << 3), b_kh = (lane >> 3) & 1;

    float acc[MT][4][4];
    #pragma unroll
    for (int mi = 0; mi < MT; mi++)
        #pragma unroll
        for (int ni = 0; ni < 4; ni++)
            #pragma unroll
            for (int q = 0; q < 4; q++) acc[mi][ni][q] = 0.f;

    #pragma unroll 1
    for (int sp = 0; sp < 2*S; sp++){
        const int s  = sp >> 1;
        const int tt = sp & 1;
        __syncthreads();
        if (tt == 0){
            const int cb = s*32;
            #pragma unroll 1
            for (int idx = t; idx < NB4; idx += 256){
                int kcq = idx & 3, p = idx >> 2;
                int d = p / PXW, h = p - d*PXW;
                int r = y + d - 1, gx = x0 + h - 1;
                uint32_t sa = smb + ASZ + swz((uint32_t)(p*64 + kcq*16));
                if (h < XT+2 && (unsigned)r < 256u && (unsigned)gx < 256u)
                    cpa16(sa, in + ((size_t)(r*256 + gx))*CIN + cb + kcq*8);
                else
                    *(uint4*)(sm + (sa - smb)) = make_uint4(0u,0u,0u,0u);
            }
        }
        const uint4* ws = (const uint4*)wA + (size_t)(s*2 + tt)*NA4;
        #pragma unroll 1
        for (int idx = t; idx < NA4; idx += 256)
            cpa16(smb + swz((uint32_t)idx*16), ws + idx);
        cpa_wait();
        __syncthreads();

        #pragma unroll
        for (int kk = 0; kk < 32; kk += 16){
            #pragma unroll
            for (int tap = 0; tap < 9; tap++){
                const int dy = tap/3, dx = tap - dy*3;
                uint32_t af[MT][4], bf[2][4];
                #pragma unroll
                for (int mi = 0; mi < MT; mi++){
                    uint32_t la = (uint32_t)(((tap*COUT + mbase + mi*16 + a_row)*32 + kk + a_kh*8)*2);
                    ldsm4(af[mi], smb + swz(la));
                }
                #pragma unroll
                for (int nh = 0; nh < 2; nh++){
                    uint32_t lb = (uint32_t)(((dy*PXW + nbase + nh*16 + b_n + dx)*32 + kk + b_kh*8)*2);
                    ldsm4(bf[nh], smb + ASZ + swz(lb));
                }
                #pragma unroll
                for (int mi = 0; mi < MT; mi++)
                    #pragma unroll
                    for (int ni = 0; ni < 4; ni++)
                        mma16816(acc[mi][ni], af[mi], bf[ni>>1][(ni&1)*2], bf[ni>>1][(ni&1)*2 + 1]);
            }
        }
    }

    __syncthreads();
    if (OMODE == 0){
        __half* tile = (__half*)sm;                  // [XT][COUT]
        #pragma unroll
        for (int mi = 0; mi < MT; mi++){
            int m0 = mbase + mi*16 + g;
            float b0v = bias[m0], b1v = bias[m0+8];
            #pragma unroll
            for (int ni = 0; ni < 4; ni++){
                int n = nbase + ni*8 + 2*tr;
                float v00 = acc[mi][ni][0] + b0v, v01 = acc[mi][ni][1] + b0v;
                float v10 = acc[mi][ni][2] + b1v, v11 = acc[mi][ni][3] + b1v;
                if (RELU){ v00=fmaxf(v00,0.f); v01=fmaxf(v01,0.f); v10=fmaxf(v10,0.f); v11=fmaxf(v11,0.f); }
                tile[ n   *COUT + m0    ] = __float2half(v00);
                tile[(n+1)*COUT + m0    ] = __float2half(v01);
                tile[ n   *COUT + m0 + 8] = __float2half(v10);
                tile[(n+1)*COUT + m0 + 8] = __float2half(v11);
            }
        }
        __syncthreads();
        uint4* dst = (uint4*)(outb + (size_t)(y*256 + x0)*COUT);
        const uint4* src = (const uint4*)sm;
        #pragma unroll 1
        for (int i = t; i < XT*COUT/8; i += 256) dst[i] = src[i];
    } else {
        float* tile = (float*)sm;                    // [XT][33]
        #pragma unroll
        for (int mi = 0; mi < MT; mi++){
            int m0 = mbase + mi*16 + g;
            float b0v = bias[m0], b1v = bias[m0+8];
            #pragma unroll
            for (int ni = 0; ni < 4; ni++){
                int n = nbase + ni*8 + 2*tr;
                float v00 = acc[mi][ni][0] + b0v, v01 = acc[mi][ni][1] + b0v;
                float v10 = acc[mi][ni][2] + b1v, v11 = acc[mi][ni][3] + b1v;
                if (RELU){ v00=fmaxf(v00,0.f); v01=fmaxf(v01,0.f); v10=fmaxf(v10,0.f); v11=fmaxf(v11,0.f); }
                tile[ n   *33 + m0    ] = v00;
                tile[(n+1)*33 + m0    ] = v01;
                tile[ n   *33 + m0 + 8] = v10;
                tile[(n+1)*33 + m0 + 8] = v11;
            }
        }
        __syncthreads();
        #pragma unroll 1
        for (int co = 0; co < COUT; co++)
            outf[(size_t)co*NPIX + y*256 + t] = tile[t*33 + co];
    }
}

// ---------------- masked covariance + FC ----------------
__global__ void __launch_bounds__(256) k_cov(const float* __restrict__ f3){
    const int k = blockIdx.y;
    const int chunk = blockIdx.x;
    const int n0 = chunk*4096;
    const int t = threadIdx.x;
    __shared__ float ftile[32*257];
    const int pt = t & 63, pg = t >> 6;
    const int ci0 = (pt & 7)*4, di0 = (pt >> 3)*4;
    float acc[4][4];
    #pragma unroll
    for (int a = 0; a < 4; a++)
        #pragma unroll
        for (int b = 0; b < 4; b++) acc[a][b] = 0.f;
    #pragma unroll 1
    for (int st = 0; st < 16; st++){
        int nb = n0 + st*256;
        __syncthreads();
        float mk = ((g_bits[nb + t] >> k) & 1) ? 1.f : 0.f;
        #pragma unroll
        for (int c = 0; c < 32; c++)
            ftile[c*257 + t] = f3[c*NPIX + nb + t] * mk;
        __syncthreads();
        for (int p = pg; p < 256; p += 4){
            float fc[4], fd[4];
            #pragma unroll
            for (int q = 0; q < 4; q++){
                fc[q] = ftile[(ci0+q)*257 + p];
                fd[q] = ftile[(di0+q)*257 + p];
            }
            #pragma unroll
            for (int a = 0; a < 4; a++)
                #pragma unroll
                for (int b = 0; b < 4; b++)
                    acc[a][b] += fd[a]*fc[b];
        }
    }
    __syncthreads();
    float* red = ftile;
    #pragma unroll
    for (int a = 0; a < 4; a++)
        #pragma unroll
        for (int b = 0; b < 4; b++)
            red[(pg*64 + pt)*16 + a*4 + b] = acc[a][b];
    __syncthreads();
    if (pg == 0){
        #pragma unroll
        for (int e = 0; e < 16; e++){
            float s = red[pt*16+e] + red[(64+pt)*16+e] + red[(128+pt)*16+e] + red[(192+pt)*16+e];
            int a = e >> 2, b = e & 3;
            g_covpart[(k*16 + chunk)*1024 + (di0+a)*32 + (ci0+b)] = s;
        }
    }
}
__global__ void k_covreduce(){
    int e = blockIdx.x*256 + threadIdx.x;
    int k = e >> 10;
    float s = 0.f;
    #pragma unroll
    for (int ch = 0; ch < 16; ch++) s += g_covpart[(k*16 + ch)*1024 + (e & 1023)];
    g_cov[e] = s / fmaxf((float)g_counts[k], 1.f);
}
__global__ void k_trans(const float* __restrict__ fcw, const float* __restrict__ fcb,
                        float* __restrict__ out){
    int gid = blockIdx.x*256 + threadIdx.x;
    int k = gid >> 10, j = gid & 1023;
    float s = fcb[j];
    const float* cv = g_cov + k*1024;
    const float* wr = fcw + j*1024;
    #pragma unroll 8
    for (int i = 0; i < 1024; i++) s += cv[i]*wr[i];
    if (g_counts[k] < 10) s = 0.f;
    out[gid] = s;
}

// ---------------- launcher ----------------
extern "C" void kernel_launch(void* const* d_in, const int* in_sizes, int n_in,
                              void* d_out, int out_size)
{
    const float* x     = (const float*)d_in[0];
    const int*   masks = (const int*)  d_in[1];
    const float* w1    = (const float*)d_in[2];
    const float* b1    = (const float*)d_in[3];
    const float* w2    = (const float*)d_in[4];
    const float* b2    = (const float*)d_in[5];
    const float* w3    = (const float*)d_in[6];
    const float* b3    = (const float*)d_in[7];
    const float* fcw   = (const float*)d_in[8];
    const float* fcb   = (const float*)d_in[9];

    float* out       = (float*)d_out;
    float* out_trans = out;
    float* out_fsm   = out + KMASK*32*32;

    void* p;
    cudaGetSymbolAddress(&p, g_xb);  __half* xb  = (__half*)p;
    cudaGetSymbolAddress(&p, g_f1);  __half* f1  = (__half*)p;
    cudaGetSymbolAddress(&p, g_f2);  __half* f2  = (__half*)p;
    cudaGetSymbolAddress(&p, g_f3);  float*  f3  = (float*)p;
    cudaGetSymbolAddress(&p, g_wA1); __half* wA1 = (__half*)p;
    cudaGetSymbolAddress(&p, g_wA2); __half* wA2 = (__half*)p;
    cudaGetSymbolAddress(&p, g_wA3); __half* wA3 = (__half*)p;

    const int SM1 = 9*128*64 + 3*132*64;   // 99072
    const int SM2 = 9*64*64  + 3*260*64;   // 86784
    const int SM3 = 9*32*64  + 3*260*64;   // 68352

    cudaFuncSetAttribute(k_convmma<256,128,4,64,true ,0>, cudaFuncAttributeMaxDynamicSharedMemorySize, SM1);
    cudaFuncSetAttribute(k_convmma<128, 64,8,64,true ,0>, cudaFuncAttributeMaxDynamicSharedMemorySize, SM2);
    cudaFuncSetAttribute(k_convmma< 64, 32,8,32,false,1>, cudaFuncAttributeMaxDynamicSharedMemorySize, SM3);

    // launch order chosen so conv1 is the 6th launch (ncu -s 5 -c 1 profiles it)
    k_repackAll<<<(16*9*128*32 + 8*9*64*32 + 4*9*32*32 + 255)/256, 256>>>(w1, w2, w3);
    k_maskbits<<<256, 256>>>(masks);
    k_sums<<<dim3(256, 8), 256>>>(x);
    k_meanvalid<<<1, 256>>>();
    k_fsm<<<256, 256>>>(x, out_fsm);

    k_convmma<256,128,4,64,true ,0><<<dim3(2,256), 256, SM1>>>(xb, wA1, b1, nullptr, f1);
    k_convmma<128, 64,8,64,true ,0><<<dim3(1,256), 256, SM2>>>(f1, wA2, b2, nullptr, f2);
    k_convmma< 64, 32,8,32,false,1><<<dim3(1,256), 256, SM3>>>(f2, wA3, b3, f3, nullptr);

    k_cov<<<dim3(16, 9), 256>>>(f3);
    k_covreduce<<<36, 256>>>();
    k_trans<<<36, 256>>>(fcw, fcb, out_trans);
}

// round 7
// speedup vs baseline: 3.4249x; 1.2484x over previous
#include <cuda_runtime.h>
#include <cuda_fp16.h>
#include <cstdint>

#define NPIX  65536
#define KMASK 9

// ---------------- device-global scratch ----------------
__device__ __align__(16) __half g_xb [(size_t)NPIX*256];   // fsm fp16 HWC
__device__ __align__(16) __half g_f1 [(size_t)NPIX*128];   // feat1 fp16 HWC
__device__ __align__(16) __half g_f2 [(size_t)NPIX*64];    // feat2 fp16 HWC
__device__ float  g_f3 [32*NPIX];                          // feat3 fp32 [c][n]
__device__ __align__(16) __half g_wA1[8*9*128*32];         // [s][tap][co][ci32]
__device__ __align__(16) __half g_wA2[4*9*64*32];
__device__ __align__(16) __half g_wA3[2*9*32*32];
__device__ int   g_bits  [NPIX];
__device__ int   g_cntpart[256][KMASK];
__device__ float g_Spart [8][KMASK][256];
__device__ int   g_counts[KMASK];
__device__ float g_mean  [KMASK*256];
__device__ unsigned g_validbits;
__device__ float g_covpart[KMASK*16*1024];
__device__ float g_cov    [KMASK*1024];

// ---------------- helpers ----------------
__device__ __forceinline__ uint32_t s2u(const void* p){
    uint32_t a;
    asm("{ .reg .u64 t; cvta.to.shared.u64 t, %1; cvt.u32.u64 %0, t; }" : "=r"(a) : "l"(p));
    return a;
}
__device__ __forceinline__ uint32_t swz(uint32_t b){   // kill 64B-stride ldmatrix conflicts
    return b ^ (((b >> 7) & 3u) << 4);
}
__device__ __forceinline__ void ldsm4(uint32_t* r, uint32_t addr){
    asm volatile("ldmatrix.sync.aligned.m8n8.x4.shared.b16 {%0,%1,%2,%3}, [%4];"
        : "=r"(r[0]), "=r"(r[1]), "=r"(r[2]), "=r"(r[3]) : "r"(addr));
}
__device__ __forceinline__ void mma16816(float* c, const uint32_t* a, uint32_t b0, uint32_t b1){
    asm volatile("mma.sync.aligned.m16n8k16.row.col.f32.f16.f16.f32 "
        "{%0,%1,%2,%3},{%4,%5,%6,%7},{%8,%9},{%0,%1,%2,%3};"
        : "+f"(c[0]), "+f"(c[1]), "+f"(c[2]), "+f"(c[3])
        : "r"(a[0]), "r"(a[1]), "r"(a[2]), "r"(a[3]), "r"(b0), "r"(b1));
}
__device__ __forceinline__ void cpa16(uint32_t s, const void* g){
    asm volatile("cp.async.cg.shared.global [%0], [%1], 16;" :: "r"(s), "l"(g));
}
__device__ __forceinline__ void cpa_wait(){
    asm volatile("cp.async.commit_group;");
    asm volatile("cp.async.wait_group 0;");
}

// ---------------- small kernels ----------------
__global__ void k_maskbits(const int* __restrict__ masks){
    int n = blockIdx.x*256 + threadIdx.x;
    int bits = 0;
    #pragma unroll
    for (int k = 0; k < KMASK; k++){
        int on = (masks[k*NPIX + n] > 0) ? 1 : 0;
        bits |= on << k;
        int c = __syncthreads_count(on);
        if (threadIdx.x == 0) g_cntpart[blockIdx.x][k] = c;   // deterministic partials
    }
    g_bits[n] = bits;
}
__global__ void k_sums(const float* __restrict__ x){
    const int c = blockIdx.x, s = blockIdx.y, t = threadIdx.x;
    float ls[KMASK];
    #pragma unroll
    for (int k = 0; k < KMASK; k++) ls[k] = 0.f;
    const float* xc = x + c*NPIX + s*8192;
    const int*   bp = g_bits + s*8192;
    for (int i = 0; i < 32; i++){
        float v = xc[i*256 + t];
        int   b = bp[i*256 + t];
        #pragma unroll
        for (int k = 0; k < KMASK; k++)
            if ((b >> k) & 1) ls[k] += v;
    }
    __shared__ float red[256];
    #pragma unroll
    for (int k = 0; k < KMASK; k++){
        red[t] = ls[k];
        __syncthreads();
        for (int off = 128; off > 0; off >>= 1){
            if (t < off) red[t] += red[t+off];
            __syncthreads();
        }
        if (t == 0) g_Spart[s][k][c] = red[0];
        __syncthreads();
    }
}
__global__ void k_meanvalid(){
    int t = threadIdx.x;
    __shared__ int redi[256];
    __shared__ int scnt[KMASK];
    for (int k = 0; k < KMASK; k++){
        redi[t] = g_cntpart[t][k];
        __syncthreads();
        for (int off = 128; off > 0; off >>= 1){
            if (t < off) redi[t] += redi[t+off];
            __syncthreads();
        }
        if (t == 0){ scnt[k] = redi[0]; g_counts[k] = redi[0]; }
        __syncthreads();
    }
    for (int k = 0; k < KMASK; k++){
        float s = 0.f;
        #pragma unroll
        for (int p = 0; p < 8; p++) s += g_Spart[p][k][t];
        g_mean[k*256 + t] = s / fmaxf((float)scnt[k], 1.f);
    }
    if (t == 0){
        unsigned vb = 0;
        for (int k = 0; k < KMASK; k++)
            if (scnt[k] >= 10) vb |= 1u << k;
        g_validbits = vb;
    }
}

// fsm: fp32 [c][n] out + fp16 HWC plane
__global__ void k_fsm(const float* __restrict__ x, float* __restrict__ out_fsm){
    int n = blockIdx.x*256 + threadIdx.x;
    unsigned ob = ((unsigned)g_bits[n]) & g_validbits;
    int krow = ob ? (31 - __clz(ob)) : -1;
    #pragma unroll 1
    for (int g = 0; g < 32; g++){
        __half bh[8];
        #pragma unroll
        for (int j = 0; j < 8; j++){
            int c = g*8 + j;
            float m = (krow >= 0) ? g_mean[krow*256 + c] : 0.f;
            float v = x[c*NPIX + n] - m;
            out_fsm[c*NPIX + n] = v;
            bh[j] = __float2half(v);
        }
        *(uint4*)&g_xb[(size_t)n*256 + g*8] = *(uint4*)bh;
    }
}

// all weights -> [s][tap][co][ci32] fp16 (single plane)
__global__ void k_repackAll(const float* __restrict__ w1, const float* __restrict__ w2,
                            const float* __restrict__ w3){
    const int N1 = 8*9*128*32, N2 = 4*9*64*32, N3 = 2*9*32*32;
    int id = blockIdx.x*256 + threadIdx.x;
    const float* w; __half* wA; int Cin, Cout, idx;
    if (id < N1)            { w = w1; wA = g_wA1; Cin = 256; Cout = 128; idx = id; }
    else if (id < N1+N2)    { w = w2; wA = g_wA2; Cin = 128; Cout =  64; idx = id - N1; }
    else if (id < N1+N2+N3) { w = w3; wA = g_wA3; Cin =  64; Cout =  32; idx = id - N1 - N2; }
    else return;
    int kci = idx & 31;
    int co  = (idx >> 5) % Cout;
    int r   = idx / (32*Cout);         // s*9 + tap
    int tap = r % 9;
    int s   = r / 9;
    wA[idx] = __float2half(w[(co*Cin + s*32 + kci)*9 + tap]);
}

// ---------------- HMMA implicit-GEMM 3x3 conv, single-term fp16 ----------------
template<int CIN, int COUT, int WN, int MW, bool RELU, int OMODE>
__global__ void __launch_bounds__(256, 2) k_convmma(
    const __half* __restrict__ in, const __half* __restrict__ wA,
    const float* __restrict__ bias, float* __restrict__ outf, __half* __restrict__ outb)
{
    constexpr int S   = CIN/32;
    constexpr int XT  = WN*32;
    constexpr int PXW = XT + 4;
    constexpr int ASZ = 9*COUT*64;     // bytes
    constexpr int MT  = MW/16;
    constexpr int NB4 = 3*PXW*4;
    constexpr int NA4 = 9*COUT*4;

    extern __shared__ __align__(1024) char sm[];
    const uint32_t smb = s2u(sm);
    const int t = threadIdx.x, w = t >> 5, lane = t & 31;
    const int wm = w / WN, wn = w % WN;
    const int mbase = wm*MW, nbase = wn*32;
    const int y = blockIdx.y, x0 = blockIdx.x*XT;
    const int g = lane >> 2, tr = lane & 3;
    const int a_row = lane & 15, a_kh = lane >> 4;
    const int b_n = (lane & 7) + ((lane >> 4) << 3), b_kh = (lane >> 3) & 1;

    float acc[MT][4][4];
    #pragma unroll
    for (int mi = 0; mi < MT; mi++)
        #pragma unroll
        for (int ni = 0; ni < 4; ni++)
            #pragma unroll
            for (int q = 0; q < 4; q++) acc[mi][ni][q] = 0.f;

    #pragma unroll 1
    for (int s = 0; s < S; s++){
        __syncthreads();
        const int cb = s*32;
        #pragma unroll 1
        for (int idx = t; idx < NB4; idx += 256){
            int kcq = idx & 3, p = idx >> 2;
            int d = p / PXW, h = p - d*PXW;
            int r = y + d - 1, gx = x0 + h - 1;
            uint32_t sa = smb + ASZ + swz((uint32_t)(p*64 + kcq*16));
            if (h < XT+2 && (unsigned)r < 256u && (unsigned)gx < 256u)
                cpa16(sa, in + ((size_t)(r*256 + gx))*CIN + cb + kcq*8);
            else
                *(uint4*)(sm + (sa - smb)) = make_uint4(0u,0u,0u,0u);
        }
        const uint4* ws = (const uint4*)wA + (size_t)s*NA4;
        #pragma unroll 1
        for (int idx = t; idx < NA4; idx += 256)
            cpa16(smb + swz((uint32_t)idx*16), ws + idx);
        cpa_wait();
        __syncthreads();

        #pragma unroll
        for (int kk = 0; kk < 32; kk += 16){
            #pragma unroll
            for (int tap = 0; tap < 9; tap++){
                const int dy = tap/3, dx = tap - dy*3;
                uint32_t af[MT][4], bf[2][4];
                #pragma unroll
                for (int mi = 0; mi < MT; mi++){
                    uint32_t la = (uint32_t)(((tap*COUT + mbase + mi*16 + a_row)*32 + kk + a_kh*8)*2);
                    ldsm4(af[mi], smb + swz(la));
                }
                #pragma unroll
                for (int nh = 0; nh < 2; nh++){
                    uint32_t lb = (uint32_t)(((dy*PXW + nbase + nh*16 + b_n + dx)*32 + kk + b_kh*8)*2);
                    ldsm4(bf[nh], smb + ASZ + swz(lb));
                }
                #pragma unroll
                for (int mi = 0; mi < MT; mi++)
                    #pragma unroll
                    for (int ni = 0; ni < 4; ni++)
                        mma16816(acc[mi][ni], af[mi], bf[ni>>1][(ni&1)*2], bf[ni>>1][(ni&1)*2 + 1]);
            }
        }
    }

    __syncthreads();
    if (OMODE == 0){
        __half* tile = (__half*)sm;                  // [XT][COUT]
        #pragma unroll
        for (int mi = 0; mi < MT; mi++){
            int m0 = mbase + mi*16 + g;
            float b0v = bias[m0], b1v = bias[m0+8];
            #pragma unroll
            for (int ni = 0; ni < 4; ni++){
                int n = nbase + ni*8 + 2*tr;
                float v00 = acc[mi][ni][0] + b0v, v01 = acc[mi][ni][1] + b0v;
                float v10 = acc[mi][ni][2] + b1v, v11 = acc[mi][ni][3] + b1v;
                if (RELU){ v00=fmaxf(v00,0.f); v01=fmaxf(v01,0.f); v10=fmaxf(v10,0.f); v11=fmaxf(v11,0.f); }
                tile[ n   *COUT + m0    ] = __float2half(v00);
                tile[(n+1)*COUT + m0    ] = __float2half(v01);
                tile[ n   *COUT + m0 + 8] = __float2half(v10);
                tile[(n+1)*COUT + m0 + 8] = __float2half(v11);
            }
        }
        __syncthreads();
        uint4* dst = (uint4*)(outb + (size_t)(y*256 + x0)*COUT);
        const uint4* src = (const uint4*)sm;
        #pragma unroll 1
        for (int i = t; i < XT*COUT/8; i += 256) dst[i] = src[i];
    } else {
        float* tile = (float*)sm;                    // [XT][33]
        #pragma unroll
        for (int mi = 0; mi < MT; mi++){
            int m0 = mbase + mi*16 + g;
            float b0v = bias[m0], b1v = bias[m0+8];
            #pragma unroll
            for (int ni = 0; ni < 4; ni++){
                int n = nbase + ni*8 + 2*tr;
                float v00 = acc[mi][ni][0] + b0v, v01 = acc[mi][ni][1] + b0v;
                float v10 = acc[mi][ni][2] + b1v, v11 = acc[mi][ni][3] + b1v;
                if (RELU){ v00=fmaxf(v00,0.f); v01=fmaxf(v01,0.f); v10=fmaxf(v10,0.f); v11=fmaxf(v11,0.f); }
                tile[ n   *33 + m0    ] = v00;
                tile[(n+1)*33 + m0    ] = v01;
                tile[ n   *33 + m0 + 8] = v10;
                tile[(n+1)*33 + m0 + 8] = v11;
            }
        }
        __syncthreads();
        #pragma unroll 1
        for (int co = 0; co < COUT; co++)
            outf[(size_t)co*NPIX + y*256 + t] = tile[t*33 + co];
    }
}

// ---------------- masked covariance + FC ----------------
__global__ void __launch_bounds__(256) k_cov(const float* __restrict__ f3){
    const int k = blockIdx.y;
    const int chunk = blockIdx.x;
    const int n0 = chunk*4096;
    const int t = threadIdx.x;
    __shared__ float ftile[32*257];
    const int pt = t & 63, pg = t >> 6;
    const int ci0 = (pt & 7)*4, di0 = (pt >> 3)*4;
    float acc[4][4];
    #pragma unroll
    for (int a = 0; a < 4; a++)
        #pragma unroll
        for (int b = 0; b < 4; b++) acc[a][b] = 0.f;
    #pragma unroll 1
    for (int st = 0; st < 16; st++){
        int nb = n0 + st*256;
        __syncthreads();
        float mk = ((g_bits[nb + t] >> k) & 1) ? 1.f : 0.f;
        #pragma unroll
        for (int c = 0; c < 32; c++)
            ftile[c*257 + t] = f3[c*NPIX + nb + t] * mk;
        __syncthreads();
        for (int p = pg; p < 256; p += 4){
            float fc[4], fd[4];
            #pragma unroll
            for (int q = 0; q < 4; q++){
                fc[q] = ftile[(ci0+q)*257 + p];
                fd[q] = ftile[(di0+q)*257 + p];
            }
            #pragma unroll
            for (int a = 0; a < 4; a++)
                #pragma unroll
                for (int b = 0; b < 4; b++)
                    acc[a][b] += fd[a]*fc[b];
        }
    }
    __syncthreads();
    float* red = ftile;
    #pragma unroll
    for (int a = 0; a < 4; a++)
        #pragma unroll
        for (int b = 0; b < 4; b++)
            red[(pg*64 + pt)*16 + a*4 + b] = acc[a][b];
    __syncthreads();
    if (pg == 0){
        #pragma unroll
        for (int e = 0; e < 16; e++){
            float s = red[pt*16+e] + red[(64+pt)*16+e] + red[(128+pt)*16+e] + red[(192+pt)*16+e];
            int a = e >> 2, b = e & 3;
            g_covpart[(k*16 + chunk)*1024 + (di0+a)*32 + (ci0+b)] = s;
        }
    }
}
__global__ void k_covreduce(){
    int e = blockIdx.x*256 + threadIdx.x;
    int k = e >> 10;
    float s = 0.f;
    #pragma unroll
    for (int ch = 0; ch < 16; ch++) s += g_covpart[(k*16 + ch)*1024 + (e & 1023)];
    g_cov[e] = s / fmaxf((float)g_counts[k], 1.f);
}
__global__ void k_trans(const float* __restrict__ fcw, const float* __restrict__ fcb,
                        float* __restrict__ out){
    int gid = blockIdx.x*256 + threadIdx.x;
    int k = gid >> 10, j = gid & 1023;
    float s = fcb[j];
    const float* cv = g_cov + k*1024;
    const float* wr = fcw + j*1024;
    #pragma unroll 8
    for (int i = 0; i < 1024; i++) s += cv[i]*wr[i];
    if (g_counts[k] < 10) s = 0.f;
    out[gid] = s;
}

// ---------------- launcher ----------------
extern "C" void kernel_launch(void* const* d_in, const int* in_sizes, int n_in,
                              void* d_out, int out_size)
{
    const float* x     = (const float*)d_in[0];
    const int*   masks = (const int*)  d_in[1];
    const float* w1    = (const float*)d_in[2];
    const float* b1    = (const float*)d_in[3];
    const float* w2    = (const float*)d_in[4];
    const float* b2    = (const float*)d_in[5];
    const float* w3    = (const float*)d_in[6];
    const float* b3    = (const float*)d_in[7];
    const float* fcw   = (const float*)d_in[8];
    const float* fcb   = (const float*)d_in[9];

    float* out       = (float*)d_out;
    float* out_trans = out;
    float* out_fsm   = out + KMASK*32*32;

    void* p;
    cudaGetSymbolAddress(&p, g_xb);  __half* xb  = (__half*)p;
    cudaGetSymbolAddress(&p, g_f1);  __half* f1  = (__half*)p;
    cudaGetSymbolAddress(&p, g_f2);  __half* f2  = (__half*)p;
    cudaGetSymbolAddress(&p, g_f3);  float*  f3  = (float*)p;
    cudaGetSymbolAddress(&p, g_wA1); __half* wA1 = (__half*)p;
    cudaGetSymbolAddress(&p, g_wA2); __half* wA2 = (__half*)p;
    cudaGetSymbolAddress(&p, g_wA3); __half* wA3 = (__half*)p;

    const int SM1 = 9*128*64 + 3*132*64;   // 99072
    const int SM2 = 9*64*64  + 3*260*64;   // 86784
    const int SM3 = 9*32*64  + 3*260*64;   // 68352

    cudaFuncSetAttribute(k_convmma<256,128,4,64,true ,0>, cudaFuncAttributeMaxDynamicSharedMemorySize, SM1);
    cudaFuncSetAttribute(k_convmma<128, 64,8,64,true ,0>, cudaFuncAttributeMaxDynamicSharedMemorySize, SM2);
    cudaFuncSetAttribute(k_convmma< 64, 32,8,32,false,1>, cudaFuncAttributeMaxDynamicSharedMemorySize, SM3);

    k_repackAll<<<(8*9*128*32 + 4*9*64*32 + 2*9*32*32 + 255)/256, 256>>>(w1, w2, w3);
    k_maskbits<<<256, 256>>>(masks);
    k_sums<<<dim3(256, 8), 256>>>(x);
    k_meanvalid<<<1, 256>>>();
    k_fsm<<<256, 256>>>(x, out_fsm);

    k_convmma<256,128,4,64,true ,0><<<dim3(2,256), 256, SM1>>>(xb, wA1, b1, nullptr, f1);
    k_convmma<128, 64,8,64,true ,0><<<dim3(1,256), 256, SM2>>>(f1, wA2, b2, nullptr, f2);
    k_convmma< 64, 32,8,32,false,1><<<dim3(1,256), 256, SM3>>>(f2, wA3, b3, f3, nullptr);

    k_cov<<<dim3(16, 9), 256>>>(f3);
    k_covreduce<<<36, 256>>>();
    k_trans<<<36, 256>>>(fcw, fcb, out_trans);
}